// round 15
// baseline (speedup 1.0000x reference)
#include <cuda_runtime.h>
#include <cstdint>
#include <cstddef>

// Problem constants (fixed shapes)
#define Tn    1024
#define Bn    128
#define In    64
#define Hn    256
#define Cn    64
#define OUTL  128
#define NCTA  128
#define NTHR  256
#define CLS   8              // cluster size == CTAs per exchange group
#define NGRP  16             // 128/8
#define RB    8              // batch rows per group
#define GC    128            // gate-cols per CTA
#define HCPC  32             // h-cols per CTA
#define ASTR  328            // activation row stride (floats), 16B multiple
#define ABUF  (RB * ASTR)    // one activation buffer (floats)
#define PBUF  (RB * 4 * GC)  // one partials buffer (floats)

typedef unsigned long long ull;

// ---------------- persistent device state ----------------
__device__ float g_decH[Bn][OUTL][Hn];       // decoder hidden states for epilogue

struct alignas(32) Flag { unsigned v; unsigned pad[7]; };
__device__ Flag g_flag[NGRP][CLS];           // per-producer counter: +1 per warp per step

// ---------------- helpers ----------------
__device__ __forceinline__ unsigned ld_acq_u32(const unsigned* p) {
    unsigned v;
    asm volatile("ld.acquire.gpu.global.u32 %0, [%1];" : "=r"(v) : "l"(p) : "memory");
    return v;
}
__device__ __forceinline__ void rel_add1(unsigned* p) {
    asm volatile("red.release.gpu.global.add.u32 [%0], %1;" :: "l"(p), "r"(1u) : "memory");
}
__device__ __forceinline__ uint32_t smem_u32(const void* p) {
    uint32_t a;
    asm("{ .reg .u64 t; cvta.to.shared.u64 t, %1; cvt.u32.u64 %0, t; }"
        : "=r"(a) : "l"(p));
    return a;
}
__device__ __forceinline__ uint32_t mapa_u32(uint32_t addr, uint32_t rank) {
    uint32_t r;
    asm("mapa.shared::cluster.u32 %0, %1, %2;" : "=r"(r) : "r"(addr), "r"(rank));
    return r;
}
__device__ __forceinline__ void st_cluster_u32(uint32_t addr, uint32_t v) {
    asm volatile("st.shared::cluster.u32 [%0], %1;" :: "r"(addr), "r"(v) : "memory");
}
#define CLUSTER_SYNC() do { \
    asm volatile("barrier.cluster.arrive.aligned;" ::: "memory"); \
    asm volatile("barrier.cluster.wait.aligned;"   ::: "memory"); \
} while (0)

__device__ __forceinline__ ull pk2(float x, float y) {
    ull r; asm("mov.b64 %0, {%1, %2};" : "=l"(r) : "f"(x), "f"(y)); return r;
}
__device__ __forceinline__ void upk2(ull v, float& x, float& y) {
    asm("mov.b64 {%0, %1}, %2;" : "=f"(x), "=f"(y) : "l"(v));
}
__device__ __forceinline__ ull ffma2(ull a, ull b, ull c) {
    ull d; asm("fma.rn.f32x2 %0, %1, %2, %3;" : "=l"(d) : "l"(a), "l"(b), "l"(c));
    return d;
}
__device__ __forceinline__ float sigf(float x) {
    return 1.0f / (1.0f + __expf(-x));
}
__device__ __forceinline__ float tanhf_fast(float x) {
    x = fminf(fmaxf(x, -15.0f), 15.0f);
    float e = __expf(2.0f * x);
    return (e - 1.0f) / (e + 1.0f);
}

// x-phase: partials over x[16kq,16kq+16) into sx[16] register array.
__device__ __forceinline__ void gemm_x(const float* __restrict__ aS,
                                       float* __restrict__ sx,
                                       const ull* __restrict__ wr, int kq)
{
    const int xoff = 16 * kq;
    #pragma unroll
    for (int rp = 0; rp < 4; ++rp) {
        const float* b0 = aS + (2 * rp) * ASTR + xoff;
        const float* b1 = b0 + ASTR;
        ull a00 = 0ull, a01 = 0ull, a10 = 0ull, a11 = 0ull;
        #pragma unroll
        for (int u = 0; u < 4; ++u) {
            ulonglong2 A0 = *(const ulonglong2*)(b0 + 4 * u);
            a00 = ffma2(A0.x, wr[4 * u + 0], a00);
            a00 = ffma2(A0.y, wr[4 * u + 1], a00);
            a01 = ffma2(A0.x, wr[4 * u + 2], a01);
            a01 = ffma2(A0.y, wr[4 * u + 3], a01);
            ulonglong2 A1 = *(const ulonglong2*)(b1 + 4 * u);
            a10 = ffma2(A1.x, wr[4 * u + 0], a10);
            a10 = ffma2(A1.y, wr[4 * u + 1], a10);
            a11 = ffma2(A1.x, wr[4 * u + 2], a11);
            a11 = ffma2(A1.y, wr[4 * u + 3], a11);
        }
        float lo, hi;
        upk2(a00, lo, hi); sx[4 * rp + 0] = lo + hi;
        upk2(a01, lo, hi); sx[4 * rp + 1] = lo + hi;
        upk2(a10, lo, hi); sx[4 * rp + 2] = lo + hi;
        upk2(a11, lo, hi); sx[4 * rp + 3] = lo + hi;
    }
}

// h-phase: accumulate h[64kq,64kq+64), optionally seeded with x partials; store to part.
template<bool WITHSX>
__device__ __forceinline__ void gemm_h(const float* __restrict__ aS,
                                       float* __restrict__ part,
                                       const float* __restrict__ sx,
                                       const ull* __restrict__ wr,
                                       int kq, int cp)
{
    const int hoff = In + 64 * kq;
    #pragma unroll
    for (int rp = 0; rp < 4; ++rp) {
        const float* b0 = aS + (2 * rp) * ASTR + hoff;
        const float* b1 = b0 + ASTR;
        ull a00, a01, a10, a11;
        if (WITHSX) {
            a00 = pk2(sx[4 * rp + 0], 0.f);
            a01 = pk2(sx[4 * rp + 1], 0.f);
            a10 = pk2(sx[4 * rp + 2], 0.f);
            a11 = pk2(sx[4 * rp + 3], 0.f);
        } else {
            a00 = a01 = a10 = a11 = 0ull;
        }
        #pragma unroll
        for (int u = 0; u < 16; ++u) {
            const ull* wp = wr + 16 + 4 * u;
            ulonglong2 A0 = *(const ulonglong2*)(b0 + 4 * u);
            a00 = ffma2(A0.x, wp[0], a00);
            a00 = ffma2(A0.y, wp[1], a00);
            a01 = ffma2(A0.x, wp[2], a01);
            a01 = ffma2(A0.y, wp[3], a01);
            ulonglong2 A1 = *(const ulonglong2*)(b1 + 4 * u);
            a10 = ffma2(A1.x, wp[0], a10);
            a10 = ffma2(A1.y, wp[1], a10);
            a11 = ffma2(A1.x, wp[2], a11);
            a11 = ffma2(A1.y, wp[3], a11);
        }
        float lo, hi, s00, s01, s10, s11;
        upk2(a00, lo, hi); s00 = lo + hi;
        upk2(a01, lo, hi); s01 = lo + hi;
        upk2(a10, lo, hi); s10 = lo + hi;
        upk2(a11, lo, hi); s11 = lo + hi;
        *(float2*)(part + ((2 * rp + 0) * 4 + kq) * GC + 2 * cp) = make_float2(s00, s01);
        *(float2*)(part + ((2 * rp + 1) * 4 + kq) * GC + 2 * cp) = make_float2(s10, s11);
    }
}

// ---------------- persistent clustered encoder + decoder kernel ----------------
extern "C" __global__ void __launch_bounds__(NTHR, 1) __cluster_dims__(CLS, 1, 1)
lstm_persistent(const float* __restrict__ x, const int* __restrict__ lengths,
                const float* __restrict__ W_ih, const float* __restrict__ W_hh,
                const float* __restrict__ b_ih, const float* __restrict__ b_hh)
{
    extern __shared__ float sm[];
    float* smA = sm;                       // [2][RB][ASTR] activations [x_t | h_t]
    float* smP = sm + 2 * ABUF;            // [2][RB][4][GC] K-quarter partials
    unsigned* sbase = (unsigned*)(smP + 2 * PBUF);

    const int tid  = threadIdx.x;
    const int lane = tid & 31;
    const int wid  = tid >> 5;             // warp wid owns batch row 'wid'
    const int grp  = blockIdx.x >> 3;      // group (cluster) 0..15
    const int rank = blockIdx.x & 7;       // rank in cluster (== %cluster_ctarank)
    const int row0 = grp * RB;

    // GEMM role: col-pair + K-quarter (warps {2kq,2kq+1} share quarter kq)
    const int cp = tid & 63;
    const int kq = tid >> 6;
    const int c0 = cp * 2, c1 = cp * 2 + 1;

    // ---- weights into registers (once): wr[0..15]=x-units, wr[16..79]=h-units ----
    ull wr[80];
    {
        const int grow0 = (c0 >> 5) * Hn + rank * HCPC + (c0 & 31);
        const int grow1 = (c1 >> 5) * Hn + rank * HCPC + (c1 & 31);
        #pragma unroll
        for (int u = 0; u < 4; ++u) {
            float w0[4], w1[4];
            #pragma unroll
            for (int j = 0; j < 4; ++j) {
                int kk = 16 * kq + 4 * u + j;
                w0[j] = W_ih[(size_t)grow0 * In + kk];
                w1[j] = W_ih[(size_t)grow1 * In + kk];
            }
            wr[4 * u + 0] = pk2(w0[0], w0[1]);
            wr[4 * u + 1] = pk2(w0[2], w0[3]);
            wr[4 * u + 2] = pk2(w1[0], w1[1]);
            wr[4 * u + 3] = pk2(w1[2], w1[3]);
        }
        #pragma unroll
        for (int u = 0; u < 16; ++u) {
            float w0[4], w1[4];
            #pragma unroll
            for (int j = 0; j < 4; ++j) {
                int kk = 64 * kq + 4 * u + j;
                w0[j] = W_hh[(size_t)grow0 * Hn + kk];
                w1[j] = W_hh[(size_t)grow1 * Hn + kk];
            }
            wr[16 + 4 * u + 0] = pk2(w0[0], w0[1]);
            wr[16 + 4 * u + 1] = pk2(w0[2], w0[3]);
            wr[16 + 4 * u + 2] = pk2(w1[0], w1[1]);
            wr[16 + 4 * u + 3] = pk2(w1[2], w1[3]);
        }
    }

    // update role: warp wid owns row wid, lane owns local h-col
    float bq0, bq1, bq2, bq3;
    {
        int c = rank * HCPC + lane;
        bq0 = b_ih[0 * Hn + c] + b_hh[0 * Hn + c];
        bq1 = b_ih[1 * Hn + c] + b_hh[1 * Hn + c];
        bq2 = b_ih[2 * Hn + c] + b_hh[2 * Hn + c];
        bq3 = b_ih[3 * Hn + c] + b_hh[3 * Hn + c];
    }
    const int ulen = lengths[row0 + wid];
    float creg = 0.0f, hreg = 0.0f;        // cell + hidden state in registers

    // ---- init: snapshot own flag, stage x_0 into buffer 0 ----
    if (tid == 0) *sbase = ld_acq_u32(&g_flag[grp][rank].v);
    if (lane < 16) {                        // warp wid stages row wid of x_0
        float4 v = *(((const float4*)(x + ((size_t)(row0 + wid) * Tn) * In)) + lane);
        *(((float4*)(smA + wid * ASTR)) + lane) = v;
    }
    __syncthreads();
    const unsigned base = *sbase;
    CLUSTER_SYNC();                         // all cluster CTAs' smem ready for pushes

    // push addresses: this lane delivers h(row wid, col rank*32+lane) to all 8 CTAs
    const uint32_t aBase   = smem_u32(smA);
    const uint32_t pushOff = (uint32_t)(wid * ASTR + In + rank * HCPC + lane) * 4u;
    uint32_t aPeer[CLS];
    #pragma unroll
    for (int d = 0; d < CLS; ++d) aPeer[d] = mapa_u32(aBase + pushOff, (uint32_t)d);

    // ---- bootstrap: deliver h_0 = 0 into everyone's buffer 0, publish ----
    {
        #pragma unroll
        for (int d = 0; d < CLS; ++d) st_cluster_u32(aPeer[d], 0u);
        __syncwarp();
        if (lane == 0) rel_add1(&g_flag[grp][rank].v);   // 8 warps -> +8: h_0 ready
    }

    // ================= encoder: 1024 steps =================
    for (int t = 0; t < Tn; ++t) {
        const float* aCur = smA + (t & 1) * ABUF;
        float*       aNxt = smA + ((t + 1) & 1) * ABUF;
        float*       pCur = smP + (t & 1) * PBUF;

        // (a) x-phase — no h dependency; overlaps peers' delivery + publish
        float sx[16];
        gemm_x(aCur, sx, wr, kq);

        // (b) poll this quarter's two producers; data already in local smem
        if (lane < 2) {
            const unsigned* fp = &g_flag[grp][2 * kq + lane].v;
            const unsigned tgt = base + 8u * (unsigned)(t + 1);
            while ((int)(ld_acq_u32(fp) - tgt) < 0) { }
        }
        __syncwarp();

        // x_{t+1} prefetch (DRAM latency hidden under h-phase)
        float4 xv;
        const bool dox = (lane < 16) && (t + 1 < Tn);
        if (dox)
            xv = *(((const float4*)(x + ((size_t)(row0 + wid) * Tn + t + 1) * In)) + lane);

        // (c) h-phase, seeded by x partials
        gemm_h<true>(aCur, pCur, sx, wr, kq, cp);
        if (dox) *(((float4*)(aNxt + wid * ASTR)) + lane) = xv;
        __syncthreads();                                   // the ONE CTA sync

        // (d) reduce + cell update for (row wid, hcol lane)
        float h2;
        {
            float g0 = bq0, g1 = bq1, g2 = bq2, g3 = bq3;
            #pragma unroll
            for (int k4 = 0; k4 < 4; ++k4) {
                const float* pr = pCur + (wid * 4 + k4) * GC + lane;
                g0 += pr[0]; g1 += pr[32]; g2 += pr[64]; g3 += pr[96];
            }
            float c2 = sigf(g1) * creg + sigf(g0) * tanhf_fast(g2);
            h2 = sigf(g3) * tanhf_fast(c2);
            if (t >= ulen) { h2 = hreg; c2 = creg; }       // freeze masked rows
            creg = c2; hreg = h2;
        }

        // (e) deliver h_{t+1} into all 8 CTAs' next buffer, publish per warp
        {
            const uint32_t bo   = (uint32_t)(((t + 1) & 1) * ABUF) * 4u;
            const uint32_t bits = __float_as_uint(h2);
            #pragma unroll
            for (int d = 0; d < CLS; ++d) st_cluster_u32(aPeer[d] + bo, bits);
            __syncwarp();
            if (lane == 0) rel_add1(&g_flag[grp][rank].v);
        }
    }

    // ================= decoder: 128 steps (gates_x = bias) =================
    for (int s = 0; s < OUTL; ++s) {
        const int u = Tn + s;
        const float* aCur = smA + (u & 1) * ABUF;
        float*       pCur = smP + (u & 1) * PBUF;

        if (lane < 2) {
            const unsigned* fp = &g_flag[grp][2 * kq + lane].v;
            const unsigned tgt = base + 8u * (unsigned)(u + 1);
            while ((int)(ld_acq_u32(fp) - tgt) < 0) { }
        }
        __syncwarp();

        gemm_h<false>(aCur, pCur, (const float*)nullptr, wr, kq, cp);
        __syncthreads();

        float h2;
        {
            float g0 = bq0, g1 = bq1, g2 = bq2, g3 = bq3;
            #pragma unroll
            for (int k4 = 0; k4 < 4; ++k4) {
                const float* pr = pCur + (wid * 4 + k4) * GC + lane;
                g0 += pr[0]; g1 += pr[32]; g2 += pr[64]; g3 += pr[96];
            }
            float c2 = sigf(g1) * creg + sigf(g0) * tanhf_fast(g2);
            h2 = sigf(g3) * tanhf_fast(c2);
            creg = c2; hreg = h2;
        }
        g_decH[row0 + wid][s][rank * HCPC + lane] = h2;    // for epilogue MLP

        if (s + 1 < OUTL) {
            const uint32_t bo   = (uint32_t)(((u + 1) & 1) * ABUF) * 4u;
            const uint32_t bits = __float_as_uint(h2);
            #pragma unroll
            for (int d = 0; d < CLS; ++d) st_cluster_u32(aPeer[d] + bo, bits);
            __syncwarp();
            if (lane == 0) rel_add1(&g_flag[grp][rank].v);
        }
    }

    // no CTA may exit while peers could still push into its SMEM
    CLUSTER_SYNC();
}

// ---------------- epilogue: out = relu(decH @ W1^T + b1) @ W2^T + b2 ----------------
extern "C" __global__ void __launch_bounds__(256, 1)
mlp_epilogue(const float* __restrict__ W1, const float* __restrict__ b1,
             const float* __restrict__ W2, const float* __restrict__ b2,
             float* __restrict__ out)
{
    extern __shared__ float sm[];
    float* As = sm;            // [32][256] decoder h tile
    float* Hs = sm + 32 * 256; // [32][256] relu hidden tile

    const int tid  = threadIdx.x;
    const int lane = tid & 31;
    const int w    = tid >> 5;
    const int m0   = blockIdx.x * 32;

    const float* dh = &g_decH[0][0][0];
    for (int idx = tid; idx < 32 * (Hn / 4); idx += 256) {
        int r = idx >> 6, c4 = idx & 63;
        *(((float4*)(As + r * Hn)) + c4) =
            *(((const float4*)(dh + (size_t)(m0 + r) * Hn)) + c4);
    }
    __syncthreads();

    {
        const int h = w * 32 + lane;
        float acc[32];
        const float bv = b1[h];
        #pragma unroll
        for (int r = 0; r < 32; ++r) acc[r] = bv;
        for (int k = 0; k < Hn; k += 4) {
            float4 wv = *(const float4*)(W1 + (size_t)h * Hn + k);
            #pragma unroll
            for (int r = 0; r < 32; ++r) {
                float4 av = *(const float4*)(As + r * Hn + k);
                acc[r] = fmaf(av.x, wv.x, fmaf(av.y, wv.y,
                         fmaf(av.z, wv.z, fmaf(av.w, wv.w, acc[r]))));
            }
        }
        #pragma unroll
        for (int r = 0; r < 32; ++r) Hs[r * Hn + h] = fmaxf(acc[r], 0.0f);
    }
    __syncthreads();

    {
        float o[4][2];
        const float ba = b2[lane];
        const float bb = b2[lane + 32];
        #pragma unroll
        for (int ri = 0; ri < 4; ++ri) { o[ri][0] = ba; o[ri][1] = bb; }
        for (int k = 0; k < Hn; k += 4) {
            float4 wa = *(const float4*)(W2 + (size_t)lane * Hn + k);
            float4 wb = *(const float4*)(W2 + (size_t)(lane + 32) * Hn + k);
            #pragma unroll
            for (int ri = 0; ri < 4; ++ri) {
                float4 hv = *(const float4*)(Hs + (w * 4 + ri) * Hn + k);
                o[ri][0] = fmaf(hv.x, wa.x, fmaf(hv.y, wa.y,
                           fmaf(hv.z, wa.z, fmaf(hv.w, wa.w, o[ri][0]))));
                o[ri][1] = fmaf(hv.x, wb.x, fmaf(hv.y, wb.y,
                           fmaf(hv.z, wb.z, fmaf(hv.w, wb.w, o[ri][1]))));
            }
        }
        #pragma unroll
        for (int ri = 0; ri < 4; ++ri) {
            size_t m = (size_t)(m0 + w * 4 + ri);
            out[m * Cn + lane]      = o[ri][0];
            out[m * Cn + lane + 32] = o[ri][1];
        }
    }
}

// ---------------- launch ----------------
extern "C" void kernel_launch(void* const* d_in, const int* in_sizes, int n_in,
                              void* d_out, int out_size) {
    // input order: x, lengths, [out_lengths], W_ih, W_hh, b_ih, b_hh, W1, b1, W2, b2
    const int off = (n_in >= 11) ? 3 : 2;
    const float* x       = (const float*)d_in[0];
    const int*   lengths = (const int*)  d_in[1];
    const float* W_ih    = (const float*)d_in[off + 0];
    const float* W_hh    = (const float*)d_in[off + 1];
    const float* b_ih    = (const float*)d_in[off + 2];
    const float* b_hh    = (const float*)d_in[off + 3];
    const float* W1      = (const float*)d_in[off + 4];
    const float* b1      = (const float*)d_in[off + 5];
    const float* W2      = (const float*)d_in[off + 6];
    const float* b2      = (const float*)d_in[off + 7];
    float*       out     = (float*)d_out;

    const size_t smem1 = (size_t)(2 * ABUF + 2 * PBUF) * sizeof(float) + 16;  // ~53.8 KB
    const size_t smem2 = (size_t)2 * 32 * Hn * sizeof(float);                 // 64 KB

    cudaFuncSetAttribute(lstm_persistent,
                         cudaFuncAttributeMaxDynamicSharedMemorySize, (int)smem1);
    cudaFuncSetAttribute(mlp_epilogue,
                         cudaFuncAttributeMaxDynamicSharedMemorySize, (int)smem2);

    lstm_persistent<<<NCTA, NTHR, smem1>>>(x, lengths, W_ih, W_hh, b_ih, b_hh);
    mlp_epilogue<<<(Bn * OUTL) / 32, 256, smem2>>>(W1, b1, W2, b2, out);
}

// round 16
// speedup vs baseline: 1.7922x; 1.7922x over previous
#include <cuda_runtime.h>
#include <cstdint>
#include <cstddef>

// Problem constants (fixed shapes)
#define Tn    1024
#define Bn    128
#define In    64
#define Hn    256
#define Cn    64
#define OUTL  128
#define NCTA  128
#define NTHR  256
#define GRP   8              // CTAs per exchange group
#define NGRP  16             // 128/8
#define RB    8              // batch rows per group
#define GC    128            // gate-cols per CTA
#define HCPC  32             // h-cols per CTA
#define ASTR  328            // activation row stride (floats), 16B multiple
#define ABUF  (RB * ASTR)    // one activation buffer (floats)
#define PBUF  (RB * 4 * GC)  // one partials buffer (floats)

typedef unsigned long long ull;

// ---------------- persistent device state ----------------
__device__ float g_h[2][NGRP][RB][Hn];       // double-buffered hidden state (h_t -> buf t&1)
__device__ float g_decH[Bn][OUTL][Hn];       // decoder hidden states for epilogue

struct alignas(32) Flag { unsigned v; unsigned pad[7]; };
__device__ Flag g_flag[NGRP][GRP];           // per-producer counter: +1 per warp per step

// ---------------- helpers ----------------
__device__ __forceinline__ unsigned ld_acq_u32(const unsigned* p) {
    unsigned v;
    asm volatile("ld.acquire.gpu.global.u32 %0, [%1];" : "=r"(v) : "l"(p) : "memory");
    return v;
}
__device__ __forceinline__ void rel_add1(unsigned* p) {
    asm volatile("red.release.gpu.global.add.u32 [%0], %1;" :: "l"(p), "r"(1u) : "memory");
}
__device__ __forceinline__ ull pk2(float x, float y) {
    ull r; asm("mov.b64 %0, {%1, %2};" : "=l"(r) : "f"(x), "f"(y)); return r;
}
__device__ __forceinline__ void upk2(ull v, float& x, float& y) {
    asm("mov.b64 {%0, %1}, %2;" : "=f"(x), "=f"(y) : "l"(v));
}
__device__ __forceinline__ ull ffma2(ull a, ull b, ull c) {
    ull d; asm("fma.rn.f32x2 %0, %1, %2, %3;" : "=l"(d) : "l"(a), "l"(b), "l"(c));
    return d;
}
__device__ __forceinline__ float sigf(float x) {
    return 1.0f / (1.0f + __expf(-x));
}
__device__ __forceinline__ float tanhf_fast(float x) {
    x = fminf(fmaxf(x, -15.0f), 15.0f);
    float e = __expf(2.0f * x);
    return (e - 1.0f) / (e + 1.0f);
}

// x-phase: partials over x[16kq,16kq+16) into sx[16] register array.
__device__ __forceinline__ void gemm_x(const float* __restrict__ aS,
                                       float* __restrict__ sx,
                                       const ull* __restrict__ wr, int kq)
{
    const int xoff = 16 * kq;
    #pragma unroll
    for (int rp = 0; rp < 4; ++rp) {
        const float* b0 = aS + (2 * rp) * ASTR + xoff;
        const float* b1 = b0 + ASTR;
        ull a00 = 0ull, a01 = 0ull, a10 = 0ull, a11 = 0ull;
        #pragma unroll
        for (int u = 0; u < 4; ++u) {
            ulonglong2 A0 = *(const ulonglong2*)(b0 + 4 * u);
            a00 = ffma2(A0.x, wr[4 * u + 0], a00);
            a00 = ffma2(A0.y, wr[4 * u + 1], a00);
            a01 = ffma2(A0.x, wr[4 * u + 2], a01);
            a01 = ffma2(A0.y, wr[4 * u + 3], a01);
            ulonglong2 A1 = *(const ulonglong2*)(b1 + 4 * u);
            a10 = ffma2(A1.x, wr[4 * u + 0], a10);
            a10 = ffma2(A1.y, wr[4 * u + 1], a10);
            a11 = ffma2(A1.x, wr[4 * u + 2], a11);
            a11 = ffma2(A1.y, wr[4 * u + 3], a11);
        }
        float lo, hi;
        upk2(a00, lo, hi); sx[4 * rp + 0] = lo + hi;
        upk2(a01, lo, hi); sx[4 * rp + 1] = lo + hi;
        upk2(a10, lo, hi); sx[4 * rp + 2] = lo + hi;
        upk2(a11, lo, hi); sx[4 * rp + 3] = lo + hi;
    }
}

// h-phase sub-range: accumulate h-units [U0,U1) of quarter kq into acc[16] (packed).
template<int U0, int U1>
__device__ __forceinline__ void gemm_h_part(const float* __restrict__ aS,
                                            ull* __restrict__ acc,
                                            const ull* __restrict__ wr, int kq)
{
    const int hoff = In + 64 * kq;
    #pragma unroll
    for (int rp = 0; rp < 4; ++rp) {
        const float* b0 = aS + (2 * rp) * ASTR + hoff;
        const float* b1 = b0 + ASTR;
        ull a00 = acc[4 * rp + 0], a01 = acc[4 * rp + 1];
        ull a10 = acc[4 * rp + 2], a11 = acc[4 * rp + 3];
        #pragma unroll
        for (int u = U0; u < U1; ++u) {
            const ull* wp = wr + 16 + 4 * u;
            ulonglong2 A0 = *(const ulonglong2*)(b0 + 4 * u);
            a00 = ffma2(A0.x, wp[0], a00);
            a00 = ffma2(A0.y, wp[1], a00);
            a01 = ffma2(A0.x, wp[2], a01);
            a01 = ffma2(A0.y, wp[3], a01);
            ulonglong2 A1 = *(const ulonglong2*)(b1 + 4 * u);
            a10 = ffma2(A1.x, wp[0], a10);
            a10 = ffma2(A1.y, wp[1], a10);
            a11 = ffma2(A1.x, wp[2], a11);
            a11 = ffma2(A1.y, wp[3], a11);
        }
        acc[4 * rp + 0] = a00; acc[4 * rp + 1] = a01;
        acc[4 * rp + 2] = a10; acc[4 * rp + 3] = a11;
    }
}

// ---------------- persistent encoder + decoder kernel ----------------
extern "C" __global__ void __launch_bounds__(NTHR, 1)
lstm_persistent(const float* __restrict__ x, const int* __restrict__ lengths,
                const float* __restrict__ W_ih, const float* __restrict__ W_hh,
                const float* __restrict__ b_ih, const float* __restrict__ b_hh)
{
    extern __shared__ float sm[];
    float* smA = sm;                       // [2][RB][ASTR] activations [x_t | h_t]
    float* smP = sm + 2 * ABUF;            // [2][RB][4][GC] K-quarter partials
    unsigned* sbase = (unsigned*)(smP + 2 * PBUF);

    const int tid  = threadIdx.x;
    const int lane = tid & 31;
    const int wid  = tid >> 5;             // warp wid owns batch row 'wid' in update
    const int grp  = blockIdx.x >> 3;      // group 0..15
    const int rank = blockIdx.x & 7;       // rank in group 0..7
    const int row0 = grp * RB;

    // GEMM role: col-pair + K-quarter (warps {2kq,2kq+1} share quarter kq)
    const int cp = tid & 63;
    const int kq = tid >> 6;
    const int c0 = cp * 2, c1 = cp * 2 + 1;

    // ---- weights into registers (once): wr[0..15]=x-units, wr[16..79]=h-units ----
    ull wr[80];
    {
        const int grow0 = (c0 >> 5) * Hn + rank * HCPC + (c0 & 31);
        const int grow1 = (c1 >> 5) * Hn + rank * HCPC + (c1 & 31);
        #pragma unroll
        for (int u = 0; u < 4; ++u) {
            float w0[4], w1[4];
            #pragma unroll
            for (int j = 0; j < 4; ++j) {
                int kk = 16 * kq + 4 * u + j;
                w0[j] = W_ih[(size_t)grow0 * In + kk];
                w1[j] = W_ih[(size_t)grow1 * In + kk];
            }
            wr[4 * u + 0] = pk2(w0[0], w0[1]);
            wr[4 * u + 1] = pk2(w0[2], w0[3]);
            wr[4 * u + 2] = pk2(w1[0], w1[1]);
            wr[4 * u + 3] = pk2(w1[2], w1[3]);
        }
        #pragma unroll
        for (int u = 0; u < 16; ++u) {
            float w0[4], w1[4];
            #pragma unroll
            for (int j = 0; j < 4; ++j) {
                int kk = 64 * kq + 4 * u + j;
                w0[j] = W_hh[(size_t)grow0 * Hn + kk];
                w1[j] = W_hh[(size_t)grow1 * Hn + kk];
            }
            wr[16 + 4 * u + 0] = pk2(w0[0], w0[1]);
            wr[16 + 4 * u + 1] = pk2(w0[2], w0[3]);
            wr[16 + 4 * u + 2] = pk2(w1[0], w1[1]);
            wr[16 + 4 * u + 3] = pk2(w1[2], w1[3]);
        }
    }

    // update role: warp wid owns row wid, lane owns local h-col
    float bq0, bq1, bq2, bq3;
    {
        int c = rank * HCPC + lane;
        bq0 = b_ih[0 * Hn + c] + b_hh[0 * Hn + c];
        bq1 = b_ih[1 * Hn + c] + b_hh[1 * Hn + c];
        bq2 = b_ih[2 * Hn + c] + b_hh[2 * Hn + c];
        bq3 = b_ih[3 * Hn + c] + b_hh[3 * Hn + c];
    }
    const int ulen = lengths[row0 + wid];
    float creg = 0.0f, hreg = 0.0f;        // cell + hidden state in registers

    // ---- init: snapshot base, zero own h0 slab, stage x_0 into buffer 0 ----
    if (tid == 0) *sbase = ld_acq_u32(&g_flag[grp][rank].v);
    if (tid < 64) {                                    // 8 rows x 8 float4 = own slab
        int r = tid >> 3, c4 = tid & 7;
        *(((float4*)&g_h[0][grp][r][rank * HCPC]) + c4) = make_float4(0.f, 0.f, 0.f, 0.f);
    }
    if (lane < 16) {                                   // warp wid stages row wid of x_0
        float4 v = *(((const float4*)(x + ((size_t)(row0 + wid) * Tn) * In)) + lane);
        *(((float4*)(smA + wid * ASTR)) + lane) = v;
    }
    __syncthreads();
    const unsigned base = *sbase;
    if (lane == 0) rel_add1(&g_flag[grp][rank].v);     // 8 warps -> +8: h_0 published

    // ================= encoder: 1024 steps =================
    for (int t = 0; t < Tn; ++t) {
        float* aCur = smA + (t & 1) * ABUF;
        float* aNxt = smA + ((t + 1) & 1) * ABUF;
        float* pCur = smP + (t & 1) * PBUF;
        const unsigned tgt = base + 8u * (unsigned)(t + 1);

        // (a) x-phase — no h dependency; hides peers' publish latency
        float sx[16];
        gemm_x(aCur, sx, wr, kq);

        // x_{t+1} prefetch (DRAM latency hidden under h-phase)
        float4 xv;
        const bool dox = (lane < 16) && (t + 1 < Tn);
        if (dox)
            xv = *(((const float4*)(x + ((size_t)(row0 + wid) * Tn + t + 1) * In)) + lane);

        // seed accumulators with x partials
        ull acc[16];
        #pragma unroll
        for (int i = 0; i < 16; ++i) acc[i] = pk2(sx[i], 0.f);

        // (b) sub-phase A: poll + self-stage slab 2kq, GEMM k[0,32)
        {
            const int sl = 2 * kq;
            if (lane == 0) {
                const unsigned* fp = &g_flag[grp][sl].v;
                while ((int)(ld_acq_u32(fp) - tgt) < 0) { }
            }
            __syncwarp();
            const float* src = &g_h[t & 1][grp][0][sl * HCPC];
            float*       dst = aCur + In + sl * HCPC;
            #pragma unroll
            for (int j = 0; j < 2; ++j) {              // 8 rows x 8 float4, 2/lane
                int idx = lane + 32 * j, r = idx >> 3, c4 = idx & 7;
                float4 v = __ldcg(((const float4*)(src + (size_t)r * Hn)) + c4);
                *(((float4*)(dst + r * ASTR)) + c4) = v;
            }
        }
        gemm_h_part<0, 8>(aCur, acc, wr, kq);

        // (c) sub-phase B: poll + self-stage slab 2kq+1, GEMM k[32,64)
        {
            const int sl = 2 * kq + 1;
            if (lane == 0) {
                const unsigned* fp = &g_flag[grp][sl].v;
                while ((int)(ld_acq_u32(fp) - tgt) < 0) { }
            }
            __syncwarp();
            const float* src = &g_h[t & 1][grp][0][sl * HCPC];
            float*       dst = aCur + In + sl * HCPC;
            #pragma unroll
            for (int j = 0; j < 2; ++j) {
                int idx = lane + 32 * j, r = idx >> 3, c4 = idx & 7;
                float4 v = __ldcg(((const float4*)(src + (size_t)r * Hn)) + c4);
                *(((float4*)(dst + r * ASTR)) + c4) = v;
            }
        }
        gemm_h_part<8, 16>(aCur, acc, wr, kq);

        // (d) store partials
        #pragma unroll
        for (int rp = 0; rp < 4; ++rp) {
            float lo, hi, s00, s01, s10, s11;
            upk2(acc[4 * rp + 0], lo, hi); s00 = lo + hi;
            upk2(acc[4 * rp + 1], lo, hi); s01 = lo + hi;
            upk2(acc[4 * rp + 2], lo, hi); s10 = lo + hi;
            upk2(acc[4 * rp + 3], lo, hi); s11 = lo + hi;
            *(float2*)(pCur + ((2 * rp + 0) * 4 + kq) * GC + 2 * cp) = make_float2(s00, s01);
            *(float2*)(pCur + ((2 * rp + 1) * 4 + kq) * GC + 2 * cp) = make_float2(s10, s11);
        }
        if (dox) *(((float4*)(aNxt + wid * ASTR)) + lane) = xv;
        __syncthreads();                               // the ONE CTA sync

        // (e) reduce + cell update for (row wid, hcol lane)
        {
            float g0 = bq0, g1 = bq1, g2 = bq2, g3 = bq3;
            #pragma unroll
            for (int k4 = 0; k4 < 4; ++k4) {
                const float* pr = pCur + (wid * 4 + k4) * GC + lane;
                g0 += pr[0]; g1 += pr[32]; g2 += pr[64]; g3 += pr[96];
            }
            float c2 = sigf(g1) * creg + sigf(g0) * tanhf_fast(g2);
            float h2 = sigf(g3) * tanhf_fast(c2);
            if (t >= ulen) { h2 = hreg; c2 = creg; }   // freeze masked rows
            creg = c2; hreg = h2;
            __stcg(&g_h[(t + 1) & 1][grp][wid][rank * HCPC + lane], h2);
        }
        __syncwarp();
        if (lane == 0) rel_add1(&g_flag[grp][rank].v); // per-warp publish
    }

    // ================= decoder: 128 steps (gates_x = bias) =================
    for (int s = 0; s < OUTL; ++s) {
        const int u = Tn + s;
        float* aCur = smA + (u & 1) * ABUF;
        float* pCur = smP + (u & 1) * PBUF;
        const unsigned tgt = base + 8u * (unsigned)(u + 1);

        ull acc[16];
        #pragma unroll
        for (int i = 0; i < 16; ++i) acc[i] = 0ull;

        {
            const int sl = 2 * kq;
            if (lane == 0) {
                const unsigned* fp = &g_flag[grp][sl].v;
                while ((int)(ld_acq_u32(fp) - tgt) < 0) { }
            }
            __syncwarp();
            const float* src = &g_h[u & 1][grp][0][sl * HCPC];
            float*       dst = aCur + In + sl * HCPC;
            #pragma unroll
            for (int j = 0; j < 2; ++j) {
                int idx = lane + 32 * j, r = idx >> 3, c4 = idx & 7;
                float4 v = __ldcg(((const float4*)(src + (size_t)r * Hn)) + c4);
                *(((float4*)(dst + r * ASTR)) + c4) = v;
            }
        }
        gemm_h_part<0, 8>(aCur, acc, wr, kq);

        {
            const int sl = 2 * kq + 1;
            if (lane == 0) {
                const unsigned* fp = &g_flag[grp][sl].v;
                while ((int)(ld_acq_u32(fp) - tgt) < 0) { }
            }
            __syncwarp();
            const float* src = &g_h[u & 1][grp][0][sl * HCPC];
            float*       dst = aCur + In + sl * HCPC;
            #pragma unroll
            for (int j = 0; j < 2; ++j) {
                int idx = lane + 32 * j, r = idx >> 3, c4 = idx & 7;
                float4 v = __ldcg(((const float4*)(src + (size_t)r * Hn)) + c4);
                *(((float4*)(dst + r * ASTR)) + c4) = v;
            }
        }
        gemm_h_part<8, 16>(aCur, acc, wr, kq);

        #pragma unroll
        for (int rp = 0; rp < 4; ++rp) {
            float lo, hi, s00, s01, s10, s11;
            upk2(acc[4 * rp + 0], lo, hi); s00 = lo + hi;
            upk2(acc[4 * rp + 1], lo, hi); s01 = lo + hi;
            upk2(acc[4 * rp + 2], lo, hi); s10 = lo + hi;
            upk2(acc[4 * rp + 3], lo, hi); s11 = lo + hi;
            *(float2*)(pCur + ((2 * rp + 0) * 4 + kq) * GC + 2 * cp) = make_float2(s00, s01);
            *(float2*)(pCur + ((2 * rp + 1) * 4 + kq) * GC + 2 * cp) = make_float2(s10, s11);
        }
        __syncthreads();

        {
            float g0 = bq0, g1 = bq1, g2 = bq2, g3 = bq3;
            #pragma unroll
            for (int k4 = 0; k4 < 4; ++k4) {
                const float* pr = pCur + (wid * 4 + k4) * GC + lane;
                g0 += pr[0]; g1 += pr[32]; g2 += pr[64]; g3 += pr[96];
            }
            float c2 = sigf(g1) * creg + sigf(g0) * tanhf_fast(g2);
            float h2 = sigf(g3) * tanhf_fast(c2);
            creg = c2; hreg = h2;
            __stcg(&g_h[(u + 1) & 1][grp][wid][rank * HCPC + lane], h2);
            g_decH[row0 + wid][s][rank * HCPC + lane] = h2;   // for epilogue MLP
        }
        if (s + 1 < OUTL) {
            __syncwarp();
            if (lane == 0) rel_add1(&g_flag[grp][rank].v);
        }
    }
}

// ---------------- epilogue: out = relu(decH @ W1^T + b1) @ W2^T + b2 ----------------
extern "C" __global__ void __launch_bounds__(256, 1)
mlp_epilogue(const float* __restrict__ W1, const float* __restrict__ b1,
             const float* __restrict__ W2, const float* __restrict__ b2,
             float* __restrict__ out)
{
    extern __shared__ float sm[];
    float* As = sm;            // [32][256] decoder h tile
    float* Hs = sm + 32 * 256; // [32][256] relu hidden tile

    const int tid  = threadIdx.x;
    const int lane = tid & 31;
    const int w    = tid >> 5;
    const int m0   = blockIdx.x * 32;

    const float* dh = &g_decH[0][0][0];
    for (int idx = tid; idx < 32 * (Hn / 4); idx += 256) {
        int r = idx >> 6, c4 = idx & 63;
        *(((float4*)(As + r * Hn)) + c4) =
            *(((const float4*)(dh + (size_t)(m0 + r) * Hn)) + c4);
    }
    __syncthreads();

    {
        const int h = w * 32 + lane;
        float acc[32];
        const float bv = b1[h];
        #pragma unroll
        for (int r = 0; r < 32; ++r) acc[r] = bv;
        for (int k = 0; k < Hn; k += 4) {
            float4 wv = *(const float4*)(W1 + (size_t)h * Hn + k);
            #pragma unroll
            for (int r = 0; r < 32; ++r) {
                float4 av = *(const float4*)(As + r * Hn + k);
                acc[r] = fmaf(av.x, wv.x, fmaf(av.y, wv.y,
                         fmaf(av.z, wv.z, fmaf(av.w, wv.w, acc[r]))));
            }
        }
        #pragma unroll
        for (int r = 0; r < 32; ++r) Hs[r * Hn + h] = fmaxf(acc[r], 0.0f);
    }
    __syncthreads();

    {
        float o[4][2];
        const float ba = b2[lane];
        const float bb = b2[lane + 32];
        #pragma unroll
        for (int ri = 0; ri < 4; ++ri) { o[ri][0] = ba; o[ri][1] = bb; }
        for (int k = 0; k < Hn; k += 4) {
            float4 wa = *(const float4*)(W2 + (size_t)lane * Hn + k);
            float4 wb = *(const float4*)(W2 + (size_t)(lane + 32) * Hn + k);
            #pragma unroll
            for (int ri = 0; ri < 4; ++ri) {
                float4 hv = *(const float4*)(Hs + (w * 4 + ri) * Hn + k);
                o[ri][0] = fmaf(hv.x, wa.x, fmaf(hv.y, wa.y,
                           fmaf(hv.z, wa.z, fmaf(hv.w, wa.w, o[ri][0]))));
                o[ri][1] = fmaf(hv.x, wb.x, fmaf(hv.y, wb.y,
                           fmaf(hv.z, wb.z, fmaf(hv.w, wb.w, o[ri][1]))));
            }
        }
        #pragma unroll
        for (int ri = 0; ri < 4; ++ri) {
            size_t m = (size_t)(m0 + w * 4 + ri);
            out[m * Cn + lane]      = o[ri][0];
            out[m * Cn + lane + 32] = o[ri][1];
        }
    }
}

// ---------------- launch ----------------
extern "C" void kernel_launch(void* const* d_in, const int* in_sizes, int n_in,
                              void* d_out, int out_size) {
    // input order: x, lengths, [out_lengths], W_ih, W_hh, b_ih, b_hh, W1, b1, W2, b2
    const int off = (n_in >= 11) ? 3 : 2;
    const float* x       = (const float*)d_in[0];
    const int*   lengths = (const int*)  d_in[1];
    const float* W_ih    = (const float*)d_in[off + 0];
    const float* W_hh    = (const float*)d_in[off + 1];
    const float* b_ih    = (const float*)d_in[off + 2];
    const float* b_hh    = (const float*)d_in[off + 3];
    const float* W1      = (const float*)d_in[off + 4];
    const float* b1      = (const float*)d_in[off + 5];
    const float* W2      = (const float*)d_in[off + 6];
    const float* b2      = (const float*)d_in[off + 7];
    float*       out     = (float*)d_out;

    const size_t smem1 = (size_t)(2 * ABUF + 2 * PBUF) * sizeof(float) + 16;  // ~53.8 KB
    const size_t smem2 = (size_t)2 * 32 * Hn * sizeof(float);                 // 64 KB

    cudaFuncSetAttribute(lstm_persistent,
                         cudaFuncAttributeMaxDynamicSharedMemorySize, (int)smem1);
    cudaFuncSetAttribute(mlp_epilogue,
                         cudaFuncAttributeMaxDynamicSharedMemorySize, (int)smem2);

    lstm_persistent<<<NCTA, NTHR, smem1>>>(x, lengths, W_ih, W_hh, b_ih, b_hh);
    mlp_epilogue<<<(Bn * OUTL) / 32, 256, smem2>>>(W1, b1, W2, b2, out);
}

// round 17
// speedup vs baseline: 1.9830x; 1.1065x over previous
#include <cuda_runtime.h>
#include <cstdint>
#include <cstddef>

// Problem constants (fixed shapes)
#define Tn    1024
#define Bn    128
#define In    64
#define Hn    256
#define Cn    64
#define OUTL  128
#define NCTA  128
#define NTHR  256
#define GRP   8              // CTAs per exchange group
#define NGRP  16             // 128/8
#define RB    8              // batch rows per group
#define GC    128            // gate-cols per CTA
#define HCPC  32             // h-cols per CTA
#define ASTR  328            // activation row stride (floats), 16B multiple
#define ABUF  (RB * ASTR)    // one activation buffer (floats)
#define PBUF  (RB * 4 * GC)  // one partials buffer (floats)

typedef unsigned long long ull;

// ---------------- persistent device state ----------------
__device__ float g_h[2][NGRP][RB][Hn];       // double-buffered hidden state (h_t -> buf t&1)
__device__ float g_decH[Bn][OUTL][Hn];       // decoder hidden states for epilogue
__device__ float g_W1T[Hn * Hn];             // W1 transposed: [k][h]
__device__ float g_W2T[Hn * Cn];             // W2 transposed: [k][c]

struct alignas(32) Flag { unsigned v; unsigned pad[7]; };
__device__ Flag g_flag[NGRP][GRP];           // per-producer counter: +1 per warp per step

// ---------------- helpers ----------------
__device__ __forceinline__ unsigned ld_acq_u32(const unsigned* p) {
    unsigned v;
    asm volatile("ld.acquire.gpu.global.u32 %0, [%1];" : "=r"(v) : "l"(p) : "memory");
    return v;
}
__device__ __forceinline__ void rel_add1(unsigned* p) {
    asm volatile("red.release.gpu.global.add.u32 [%0], %1;" :: "l"(p), "r"(1u) : "memory");
}
__device__ __forceinline__ ull pk2(float x, float y) {
    ull r; asm("mov.b64 %0, {%1, %2};" : "=l"(r) : "f"(x), "f"(y)); return r;
}
__device__ __forceinline__ void upk2(ull v, float& x, float& y) {
    asm("mov.b64 {%0, %1}, %2;" : "=f"(x), "=f"(y) : "l"(v));
}
__device__ __forceinline__ ull ffma2(ull a, ull b, ull c) {
    ull d; asm("fma.rn.f32x2 %0, %1, %2, %3;" : "=l"(d) : "l"(a), "l"(b), "l"(c));
    return d;
}
__device__ __forceinline__ float sigf(float x) {
    return __fdividef(1.0f, 1.0f + __expf(-x));
}
__device__ __forceinline__ float tanhf_fast(float x) {
    x = fminf(fmaxf(x, -15.0f), 15.0f);
    float e = __expf(2.0f * x);
    return __fdividef(e - 1.0f, e + 1.0f);
}

// x-phase: partials over x[16kq,16kq+16) into sx[16] register array.
__device__ __forceinline__ void gemm_x(const float* __restrict__ aS,
                                       float* __restrict__ sx,
                                       const ull* __restrict__ wr, int kq)
{
    const int xoff = 16 * kq;
    #pragma unroll
    for (int rp = 0; rp < 4; ++rp) {
        const float* b0 = aS + (2 * rp) * ASTR + xoff;
        const float* b1 = b0 + ASTR;
        ull a00 = 0ull, a01 = 0ull, a10 = 0ull, a11 = 0ull;
        #pragma unroll
        for (int u = 0; u < 4; ++u) {
            ulonglong2 A0 = *(const ulonglong2*)(b0 + 4 * u);
            a00 = ffma2(A0.x, wr[4 * u + 0], a00);
            a00 = ffma2(A0.y, wr[4 * u + 1], a00);
            a01 = ffma2(A0.x, wr[4 * u + 2], a01);
            a01 = ffma2(A0.y, wr[4 * u + 3], a01);
            ulonglong2 A1 = *(const ulonglong2*)(b1 + 4 * u);
            a10 = ffma2(A1.x, wr[4 * u + 0], a10);
            a10 = ffma2(A1.y, wr[4 * u + 1], a10);
            a11 = ffma2(A1.x, wr[4 * u + 2], a11);
            a11 = ffma2(A1.y, wr[4 * u + 3], a11);
        }
        float lo, hi;
        upk2(a00, lo, hi); sx[4 * rp + 0] = lo + hi;
        upk2(a01, lo, hi); sx[4 * rp + 1] = lo + hi;
        upk2(a10, lo, hi); sx[4 * rp + 2] = lo + hi;
        upk2(a11, lo, hi); sx[4 * rp + 3] = lo + hi;
    }
}

// h-phase: accumulate h[64kq,64kq+64), optionally seeded with x partials; store to part.
template<bool WITHSX>
__device__ __forceinline__ void gemm_h(const float* __restrict__ aS,
                                       float* __restrict__ part,
                                       const float* __restrict__ sx,
                                       const ull* __restrict__ wr,
                                       int kq, int cp)
{
    const int hoff = In + 64 * kq;
    #pragma unroll
    for (int rp = 0; rp < 4; ++rp) {
        const float* b0 = aS + (2 * rp) * ASTR + hoff;
        const float* b1 = b0 + ASTR;
        ull a00, a01, a10, a11;
        if (WITHSX) {
            a00 = pk2(sx[4 * rp + 0], 0.f);
            a01 = pk2(sx[4 * rp + 1], 0.f);
            a10 = pk2(sx[4 * rp + 2], 0.f);
            a11 = pk2(sx[4 * rp + 3], 0.f);
        } else {
            a00 = a01 = a10 = a11 = 0ull;
        }
        #pragma unroll
        for (int u = 0; u < 16; ++u) {
            const ull* wp = wr + 16 + 4 * u;
            ulonglong2 A0 = *(const ulonglong2*)(b0 + 4 * u);
            a00 = ffma2(A0.x, wp[0], a00);
            a00 = ffma2(A0.y, wp[1], a00);
            a01 = ffma2(A0.x, wp[2], a01);
            a01 = ffma2(A0.y, wp[3], a01);
            ulonglong2 A1 = *(const ulonglong2*)(b1 + 4 * u);
            a10 = ffma2(A1.x, wp[0], a10);
            a10 = ffma2(A1.y, wp[1], a10);
            a11 = ffma2(A1.x, wp[2], a11);
            a11 = ffma2(A1.y, wp[3], a11);
        }
        float lo, hi, s00, s01, s10, s11;
        upk2(a00, lo, hi); s00 = lo + hi;
        upk2(a01, lo, hi); s01 = lo + hi;
        upk2(a10, lo, hi); s10 = lo + hi;
        upk2(a11, lo, hi); s11 = lo + hi;
        *(float2*)(part + ((2 * rp + 0) * 4 + kq) * GC + 2 * cp) = make_float2(s00, s01);
        *(float2*)(part + ((2 * rp + 1) * 4 + kq) * GC + 2 * cp) = make_float2(s10, s11);
    }
}

// ---------------- persistent encoder + decoder kernel (R13-verified) ----------------
extern "C" __global__ void __launch_bounds__(NTHR, 1)
lstm_persistent(const float* __restrict__ x, const int* __restrict__ lengths,
                const float* __restrict__ W_ih, const float* __restrict__ W_hh,
                const float* __restrict__ b_ih, const float* __restrict__ b_hh)
{
    extern __shared__ float sm[];
    float* smA = sm;                       // [2][RB][ASTR] activations [x_t | h_t]
    float* smP = sm + 2 * ABUF;            // [2][RB][4][GC] K-quarter partials
    unsigned* sbase = (unsigned*)(smP + 2 * PBUF);

    const int tid  = threadIdx.x;
    const int lane = tid & 31;
    const int wid  = tid >> 5;             // warp wid: stages slab 'wid', updates row 'wid'
    const int grp  = blockIdx.x >> 3;      // group 0..15
    const int rank = blockIdx.x & 7;       // rank in group 0..7
    const int row0 = grp * RB;

    // GEMM role: col-pair + K-quarter (warps {2kq,2kq+1} share quarter kq)
    const int cp = tid & 63;
    const int kq = tid >> 6;
    const int c0 = cp * 2, c1 = cp * 2 + 1;

    // ---- weights into registers (once): wr[0..15]=x-units, wr[16..79]=h-units ----
    ull wr[80];
    {
        const int grow0 = (c0 >> 5) * Hn + rank * HCPC + (c0 & 31);
        const int grow1 = (c1 >> 5) * Hn + rank * HCPC + (c1 & 31);
        #pragma unroll
        for (int u = 0; u < 4; ++u) {
            float w0[4], w1[4];
            #pragma unroll
            for (int j = 0; j < 4; ++j) {
                int kk = 16 * kq + 4 * u + j;
                w0[j] = W_ih[(size_t)grow0 * In + kk];
                w1[j] = W_ih[(size_t)grow1 * In + kk];
            }
            wr[4 * u + 0] = pk2(w0[0], w0[1]);
            wr[4 * u + 1] = pk2(w0[2], w0[3]);
            wr[4 * u + 2] = pk2(w1[0], w1[1]);
            wr[4 * u + 3] = pk2(w1[2], w1[3]);
        }
        #pragma unroll
        for (int u = 0; u < 16; ++u) {
            float w0[4], w1[4];
            #pragma unroll
            for (int j = 0; j < 4; ++j) {
                int kk = 64 * kq + 4 * u + j;
                w0[j] = W_hh[(size_t)grow0 * Hn + kk];
                w1[j] = W_hh[(size_t)grow1 * Hn + kk];
            }
            wr[16 + 4 * u + 0] = pk2(w0[0], w0[1]);
            wr[16 + 4 * u + 1] = pk2(w0[2], w0[3]);
            wr[16 + 4 * u + 2] = pk2(w1[0], w1[1]);
            wr[16 + 4 * u + 3] = pk2(w1[2], w1[3]);
        }
    }

    // update role: warp wid owns row wid, lane owns local h-col
    float bq0, bq1, bq2, bq3;
    {
        int c = rank * HCPC + lane;
        bq0 = b_ih[0 * Hn + c] + b_hh[0 * Hn + c];
        bq1 = b_ih[1 * Hn + c] + b_hh[1 * Hn + c];
        bq2 = b_ih[2 * Hn + c] + b_hh[2 * Hn + c];
        bq3 = b_ih[3 * Hn + c] + b_hh[3 * Hn + c];
    }
    const int ulen = lengths[row0 + wid];
    float creg = 0.0f;

    // ---- init: snapshot base, zero own h0 slab, stage x_0 into buffer 0 ----
    if (tid == 0) *sbase = ld_acq_u32(&g_flag[grp][rank].v);
    if (tid < 64) {                                    // 8 rows x 8 float4 = own slab
        int r = tid >> 3, c4 = tid & 7;
        *(((float4*)&g_h[0][grp][r][rank * HCPC]) + c4) = make_float4(0.f, 0.f, 0.f, 0.f);
    }
    if (lane < 16) {                                   // warp wid stages row wid of x_0
        float4 v = *(((const float4*)(x + ((size_t)(row0 + wid) * Tn) * In)) + lane);
        *(((float4*)(smA + wid * ASTR)) + lane) = v;
    }
    __syncthreads();
    const unsigned base = *sbase;
    if (lane == 0) rel_add1(&g_flag[grp][rank].v);     // 8 warps -> +8: h_0 published

    // ================= encoder: 1024 steps =================
    for (int t = 0; t < Tn; ++t) {
        float* aCur = smA + (t & 1) * ABUF;
        float* aNxt = smA + ((t + 1) & 1) * ABUF;
        float* pCur = smP + (t & 1) * PBUF;
        const unsigned tgt = base + 8u * (unsigned)(t + 1);

        // (a) x-phase — no h dependency; hides peers' publish latency
        float sx[16];
        gemm_x(aCur, sx, wr, kq);

        // (b) poll only this quarter's two producer ranks (lanes 0,1)
        if (lane < 2) {
            const unsigned* fp = &g_flag[grp][2 * kq + lane].v;
            while ((int)(ld_acq_u32(fp) - tgt) < 0) { }
        }
        __syncwarp();
        // warp 'wid' stages rank 'wid' slab (8 rows x 32 cols) from buffer t&1
        {
            const float* src = &g_h[t & 1][grp][0][wid * HCPC];
            float*       dst = aCur + In + wid * HCPC;
            #pragma unroll
            for (int j = 0; j < 2; ++j) {
                int idx = lane + 32 * j, r = idx >> 3, c4 = idx & 7;
                float4 v = __ldcg(((const float4*)(src + (size_t)r * Hn)) + c4);
                *(((float4*)(dst + r * ASTR)) + c4) = v;
            }
        }
        asm volatile("bar.sync %0, 64;" :: "r"(kq + 1) : "memory");  // pair-warp sync

        // x_{t+1} prefetch (DRAM latency hidden under h-phase)
        float4 xv;
        const bool dox = (lane < 16) && (t + 1 < Tn);
        if (dox)
            xv = *(((const float4*)(x + ((size_t)(row0 + wid) * Tn + t + 1) * In)) + lane);

        // (c) h-phase, seeded by x partials
        gemm_h<true>(aCur, pCur, sx, wr, kq, cp);
        if (dox) *(((float4*)(aNxt + wid * ASTR)) + lane) = xv;
        __syncthreads();                                   // the ONE CTA sync

        // (d) reduce + cell update for (row wid, hcol lane)
        {
            float g0 = bq0, g1 = bq1, g2 = bq2, g3 = bq3;
            #pragma unroll
            for (int k4 = 0; k4 < 4; ++k4) {
                const float* pr = pCur + (wid * 4 + k4) * GC + lane;
                g0 += pr[0]; g1 += pr[32]; g2 += pr[64]; g3 += pr[96];
            }
            float c2 = sigf(g1) * creg + sigf(g0) * tanhf_fast(g2);
            float h2 = sigf(g3) * tanhf_fast(c2);
            if (t >= ulen) {                               // freeze masked rows
                h2 = aCur[wid * ASTR + In + rank * HCPC + lane];
                c2 = creg;
            }
            creg = c2;
            __stcg(&g_h[(t + 1) & 1][grp][wid][rank * HCPC + lane], h2);
        }
        __syncwarp();
        if (lane == 0) rel_add1(&g_flag[grp][rank].v);     // per-warp publish
    }

    // ================= decoder: 128 steps (gates_x = bias) =================
    for (int s = 0; s < OUTL; ++s) {
        const int u = Tn + s;
        float* aCur = smA + (u & 1) * ABUF;
        float* pCur = smP + (u & 1) * PBUF;
        const unsigned tgt = base + 8u * (unsigned)(u + 1);

        if (lane < 2) {
            const unsigned* fp = &g_flag[grp][2 * kq + lane].v;
            while ((int)(ld_acq_u32(fp) - tgt) < 0) { }
        }
        __syncwarp();
        {
            const float* src = &g_h[u & 1][grp][0][wid * HCPC];
            float*       dst = aCur + In + wid * HCPC;
            #pragma unroll
            for (int j = 0; j < 2; ++j) {
                int idx = lane + 32 * j, r = idx >> 3, c4 = idx & 7;
                float4 v = __ldcg(((const float4*)(src + (size_t)r * Hn)) + c4);
                *(((float4*)(dst + r * ASTR)) + c4) = v;
            }
        }
        asm volatile("bar.sync %0, 64;" :: "r"(kq + 1) : "memory");

        gemm_h<false>(aCur, pCur, (const float*)nullptr, wr, kq, cp);
        __syncthreads();

        {
            float g0 = bq0, g1 = bq1, g2 = bq2, g3 = bq3;
            #pragma unroll
            for (int k4 = 0; k4 < 4; ++k4) {
                const float* pr = pCur + (wid * 4 + k4) * GC + lane;
                g0 += pr[0]; g1 += pr[32]; g2 += pr[64]; g3 += pr[96];
            }
            float c2 = sigf(g1) * creg + sigf(g0) * tanhf_fast(g2);
            float h2 = sigf(g3) * tanhf_fast(c2);
            creg = c2;
            __stcg(&g_h[(u + 1) & 1][grp][wid][rank * HCPC + lane], h2);
            g_decH[row0 + wid][s][rank * HCPC + lane] = h2;   // for epilogue MLP
        }
        if (s + 1 < OUTL) {
            __syncwarp();
            if (lane == 0) rel_add1(&g_flag[grp][rank].v);
        }
    }
}

// ---------------- weight transpose prep: W1T[k][h] = W1[h][k], W2T[k][c] = W2[c][k] ----
extern "C" __global__ void __launch_bounds__(256, 1)
transpose_prep(const float* __restrict__ W1, const float* __restrict__ W2)
{
    __shared__ float tile[32][33];
    const int b = blockIdx.x;
    const float* src; float* dst; int R, C, tb;
    if (b < 64) { src = W1; dst = g_W1T; R = Hn; C = Hn; tb = b; }        // 8x8 tiles
    else        { src = W2; dst = g_W2T; R = Cn; C = Hn; tb = b - 64; }   // 2x8 tiles
    const int tilesC = C / 32;
    const int br = (tb / tilesC) * 32;   // row origin in src
    const int bc = (tb % tilesC) * 32;   // col origin in src
    const int tx = threadIdx.x & 31, ty = threadIdx.x >> 5;
    #pragma unroll
    for (int j = 0; j < 32; j += 8)
        tile[ty + j][tx] = src[(size_t)(br + ty + j) * C + bc + tx];
    __syncthreads();
    #pragma unroll
    for (int j = 0; j < 32; j += 8)
        dst[(size_t)(bc + ty + j) * R + br + tx] = tile[tx][ty + j];
}

// ---------------- epilogue: out = relu(decH @ W1^T + b1) @ W2^T + b2 ----------------
// Uses transposed weights -> lane-contiguous (coalesced) weight loads.
// Arithmetic is bit-identical to the previous version (same values, same FMA nesting).
extern "C" __global__ void __launch_bounds__(256, 1)
mlp_epilogue(const float* __restrict__ b1, const float* __restrict__ b2,
             float* __restrict__ out)
{
    extern __shared__ float sm[];
    float* As = sm;            // [32][256] decoder h tile
    float* Hs = sm + 32 * 256; // [32][256] relu hidden tile

    const int tid  = threadIdx.x;
    const int lane = tid & 31;
    const int w    = tid >> 5;
    const int m0   = blockIdx.x * 32;

    const float* dh = &g_decH[0][0][0];
    for (int idx = tid; idx < 32 * (Hn / 4); idx += 256) {
        int r = idx >> 6, c4 = idx & 63;
        *(((float4*)(As + r * Hn)) + c4) =
            *(((const float4*)(dh + (size_t)(m0 + r) * Hn)) + c4);
    }
    __syncthreads();

    // hidden phase: warp w owns hidden cols [w*32, w*32+32), lane -> one col
    {
        const int h = w * 32 + lane;
        float acc[32];
        const float bv = b1[h];
        #pragma unroll
        for (int r = 0; r < 32; ++r) acc[r] = bv;
        for (int k = 0; k < Hn; k += 4) {
            float wv0 = g_W1T[(size_t)(k + 0) * Hn + h];   // coalesced across lanes
            float wv1 = g_W1T[(size_t)(k + 1) * Hn + h];
            float wv2 = g_W1T[(size_t)(k + 2) * Hn + h];
            float wv3 = g_W1T[(size_t)(k + 3) * Hn + h];
            #pragma unroll
            for (int r = 0; r < 32; ++r) {
                float4 av = *(const float4*)(As + r * Hn + k);
                acc[r] = fmaf(av.x, wv0, fmaf(av.y, wv1,
                         fmaf(av.z, wv2, fmaf(av.w, wv3, acc[r]))));
            }
        }
        #pragma unroll
        for (int r = 0; r < 32; ++r) Hs[r * Hn + h] = fmaxf(acc[r], 0.0f);
    }
    __syncthreads();

    // out phase: warp w owns rows w*4..w*4+3; lane -> out cols {lane, lane+32}
    {
        float o[4][2];
        const float ba = b2[lane];
        const float bb = b2[lane + 32];
        #pragma unroll
        for (int ri = 0; ri < 4; ++ri) { o[ri][0] = ba; o[ri][1] = bb; }
        for (int k = 0; k < Hn; k += 4) {
            float wa0 = g_W2T[(size_t)(k + 0) * Cn + lane];        // coalesced
            float wa1 = g_W2T[(size_t)(k + 1) * Cn + lane];
            float wa2 = g_W2T[(size_t)(k + 2) * Cn + lane];
            float wa3 = g_W2T[(size_t)(k + 3) * Cn + lane];
            float wb0 = g_W2T[(size_t)(k + 0) * Cn + lane + 32];
            float wb1 = g_W2T[(size_t)(k + 1) * Cn + lane + 32];
            float wb2 = g_W2T[(size_t)(k + 2) * Cn + lane + 32];
            float wb3 = g_W2T[(size_t)(k + 3) * Cn + lane + 32];
            #pragma unroll
            for (int ri = 0; ri < 4; ++ri) {
                float4 hv = *(const float4*)(Hs + (w * 4 + ri) * Hn + k);
                o[ri][0] = fmaf(hv.x, wa0, fmaf(hv.y, wa1,
                           fmaf(hv.z, wa2, fmaf(hv.w, wa3, o[ri][0]))));
                o[ri][1] = fmaf(hv.x, wb0, fmaf(hv.y, wb1,
                           fmaf(hv.z, wb2, fmaf(hv.w, wb3, o[ri][1]))));
            }
        }
        #pragma unroll
        for (int ri = 0; ri < 4; ++ri) {
            size_t m = (size_t)(m0 + w * 4 + ri);
            out[m * Cn + lane]      = o[ri][0];
            out[m * Cn + lane + 32] = o[ri][1];
        }
    }
}

// ---------------- launch ----------------
extern "C" void kernel_launch(void* const* d_in, const int* in_sizes, int n_in,
                              void* d_out, int out_size) {
    // input order: x, lengths, [out_lengths], W_ih, W_hh, b_ih, b_hh, W1, b1, W2, b2
    const int off = (n_in >= 11) ? 3 : 2;
    const float* x       = (const float*)d_in[0];
    const int*   lengths = (const int*)  d_in[1];
    const float* W_ih    = (const float*)d_in[off + 0];
    const float* W_hh    = (const float*)d_in[off + 1];
    const float* b_ih    = (const float*)d_in[off + 2];
    const float* b_hh    = (const float*)d_in[off + 3];
    const float* W1      = (const float*)d_in[off + 4];
    const float* b1      = (const float*)d_in[off + 5];
    const float* W2      = (const float*)d_in[off + 6];
    const float* b2      = (const float*)d_in[off + 7];
    float*       out     = (float*)d_out;

    const size_t smem1 = (size_t)(2 * ABUF + 2 * PBUF) * sizeof(float) + 16;  // ~53.8 KB
    const size_t smem2 = (size_t)2 * 32 * Hn * sizeof(float);                 // 64 KB

    cudaFuncSetAttribute(lstm_persistent,
                         cudaFuncAttributeMaxDynamicSharedMemorySize, (int)smem1);
    cudaFuncSetAttribute(mlp_epilogue,
                         cudaFuncAttributeMaxDynamicSharedMemorySize, (int)smem2);

    transpose_prep<<<80, 256>>>(W1, W2);   // W1: 64 tiles, W2: 16 tiles
    lstm_persistent<<<NCTA, NTHR, smem1>>>(x, lengths, W_ih, W_hh, b_ih, b_hh);
    mlp_epilogue<<<(Bn * OUTL) / 32, 256, smem2>>>(b1, b2, out);
}